// round 3
// baseline (speedup 1.0000x reference)
#include <cuda_runtime.h>
#include <cstddef>

#define BB 64
#define SS 256
#define DD 300
#define HH 512
#define GG 2048   // 4*H
#define KC 1024   // 2*H

// ---------------- scratch (static device globals; no allocation) ------------
__device__ float g_xz[2][(size_t)BB * SS * GG];   // per-dir input projections (268 MB)
__device__ float g_hs0[2][(size_t)BB * SS * HH];  // layer-0 seq outputs, indexed by ORIGINAL t
__device__ float g_h[2][2][BB * HH];              // [dir][parity][b*H+h]  double-buffered h
__device__ float g_c[2][BB * HH];                 // [dir][b*H+h]
__device__ float g_fc1[BB * 512];
__device__ float g_fc2[BB * 256];

// ---------------- zero h/c state -------------------------------------------
__global__ void k_zero_state() {
    int i = blockIdx.x * blockDim.x + threadIdx.x;
    if (i < BB * HH) {
        g_h[0][0][i] = 0.f; g_h[0][1][i] = 0.f;
        g_h[1][0][i] = 0.f; g_h[1][1][i] = 0.f;
        g_c[0][i]    = 0.f; g_c[1][i]    = 0.f;
    }
}

// ---------------- input-projection GEMM ------------------------------------
// MODE 0: A[r][k] = emb[text[r]][k],                    K = 300
// MODE 1: A[r][k] = k<H ? hs0_f[r][k] : hs0_b[r][k-H],  K = 1024
// out[r][j] = sum_k A[r][k] * W[k][j] + bias[j]   -> g_xz[dir]
// BM=64, BN=64, BK=16, 256 threads, 4x4 register tiles.
template<int MODE>
__global__ void k_gemm_xz(const int* __restrict__ text,
                          const float* __restrict__ emb,
                          const float* __restrict__ Wf,
                          const float* __restrict__ bf_,
                          const float* __restrict__ Wb,
                          const float* __restrict__ bb_) {
    const int K = (MODE == 0) ? DD : KC;
    const int dir = blockIdx.z;
    const float* __restrict__ W    = dir ? Wb  : Wf;
    const float* __restrict__ bias = dir ? bb_ : bf_;
    float* __restrict__ out = g_xz[dir];

    __shared__ __align__(16) float As[16][68];
    __shared__ __align__(16) float Bs[16][68];

    const int r0 = blockIdx.x * 64;
    const int j0 = blockIdx.y * 64;
    const int tid = threadIdx.x;
    const int tx = tid & 15;   // 4-col group
    const int ty = tid >> 4;   // 4-row group

    float acc[4][4] = {};

    for (int k0 = 0; k0 < K; k0 += 16) {
        // load A tile: 64 rows x 16 k
        #pragma unroll
        for (int p = 0; p < 4; p++) {
            int kk = tid & 15;
            int rr = (tid >> 4) + p * 16;
            int k = k0 + kk;
            int r = r0 + rr;
            float v = 0.f;
            if (k < K) {
                if (MODE == 0) {
                    v = emb[(size_t)text[r] * DD + k];
                } else {
                    v = (k < HH) ? g_hs0[0][(size_t)r * HH + k]
                                 : g_hs0[1][(size_t)r * HH + (k - HH)];
                }
            }
            As[kk][rr] = v;
        }
        // load W tile: 16 k x 64 j (coalesced)
        #pragma unroll
        for (int p = 0; p < 4; p++) {
            int jj = tid & 63;
            int kk = (tid >> 6) + p * 4;
            int k = k0 + kk;
            float v = (k < K) ? W[(size_t)k * GG + j0 + jj] : 0.f;
            Bs[kk][jj] = v;
        }
        __syncthreads();
        #pragma unroll
        for (int kk = 0; kk < 16; kk++) {
            float4 a4 = *(const float4*)&As[kk][ty * 4];
            float4 b4 = *(const float4*)&Bs[kk][tx * 4];
            float ar[4] = {a4.x, a4.y, a4.z, a4.w};
            float br[4] = {b4.x, b4.y, b4.z, b4.w};
            #pragma unroll
            for (int i = 0; i < 4; i++)
                #pragma unroll
                for (int j = 0; j < 4; j++)
                    acc[i][j] += ar[i] * br[j];
        }
        __syncthreads();
    }

    #pragma unroll
    for (int i = 0; i < 4; i++) {
        int r = r0 + ty * 4 + i;
        #pragma unroll
        for (int j = 0; j < 4; j++) {
            int c = j0 + tx * 4 + j;
            out[(size_t)r * GG + c] = acc[i][j] + bias[c];
        }
    }
}

// ---------------- one LSTM time step (both directions in grid) -------------
// grid = (H/8, 2dirs), block = 128.  Each block: 8 h-indices x 64 batches x 4 gates.
// Step parity double-buffers h so the h@U GEMM never races the h update.
template<bool STORE_HS>
__global__ void k_lstm_step(int p,
                            const int* __restrict__ text,
                            const float* __restrict__ Uf,
                            const float* __restrict__ Ub) {
    const int dir = blockIdx.y;
    const int t = dir ? (SS - 1 - p) : p;
    const float* __restrict__ U = dir ? Ub : Uf;
    const float* __restrict__ hprev = g_h[dir][p & 1];
    float* __restrict__ hnext = g_h[dir][(p + 1) & 1];
    float* __restrict__ cbuf = g_c[dir];
    const float* __restrict__ xz = g_xz[dir];

    const int h0 = blockIdx.x * 8;
    const int tid = threadIdx.x;
    const int tx = tid & 7;    // h offset within tile
    const int ty = tid >> 3;   // 0..15 -> batches ty*4..ty*4+3

    __shared__ __align__(16) float hs_sm[64][36];  // [b][kk], BK=32 (+4 pad)
    __shared__ float Us[4][32][8];                 // [gate][kk][h]

    float acc[4][4] = {};  // [ib][gate]

    for (int k0 = 0; k0 < HH; k0 += 32) {
        // h tile: 64 b x 32 k, float4 loads
        #pragma unroll
        for (int p2 = 0; p2 < 4; p2++) {
            int idx = tid + 128 * p2;       // 0..511 float4 slots
            int b = idx >> 3;
            int kq = idx & 7;
            float4 v = *(const float4*)&hprev[b * HH + k0 + kq * 4];
            *(float4*)&hs_sm[b][kq * 4] = v;
        }
        // U tile: 4 gates x 32 k x 8 h
        #pragma unroll
        for (int p2 = 0; p2 < 8; p2++) {
            int idx = tid + 128 * p2;       // 0..1023
            int q = idx >> 8;
            int kk = (idx >> 3) & 31;
            int hh = idx & 7;
            Us[q][kk][hh] = U[(size_t)(k0 + kk) * GG + q * HH + h0 + hh];
        }
        __syncthreads();
        #pragma unroll
        for (int kk = 0; kk < 32; kk++) {
            float u0 = Us[0][kk][tx];
            float u1 = Us[1][kk][tx];
            float u2 = Us[2][kk][tx];
            float u3 = Us[3][kk][tx];
            #pragma unroll
            for (int ib = 0; ib < 4; ib++) {
                float hv = hs_sm[ty * 4 + ib][kk];
                acc[ib][0] += hv * u0;
                acc[ib][1] += hv * u1;
                acc[ib][2] += hv * u2;
                acc[ib][3] += hv * u3;
            }
        }
        __syncthreads();
    }

    const int hid = h0 + tx;
    #pragma unroll
    for (int ib = 0; ib < 4; ib++) {
        int b = ty * 4 + ib;
        size_t r = (size_t)b * SS + t;
        float zi = acc[ib][0] + xz[r * GG + 0 * HH + hid];
        float zf = acc[ib][1] + xz[r * GG + 1 * HH + hid];
        float zg = acc[ib][2] + xz[r * GG + 2 * HH + hid];
        float zo = acc[ib][3] + xz[r * GG + 3 * HH + hid];
        float ig = 1.f / (1.f + __expf(-zi));
        float fg = 1.f / (1.f + __expf(-zf));
        float gg = tanhf(zg);
        float og = 1.f / (1.f + __expf(-zo));
        float cold = cbuf[b * HH + hid];
        float hold = hprev[b * HH + hid];
        float cn = fg * cold + ig * gg;
        float hn = og * tanhf(cn);
        bool m = (text[r] != 0);
        float cw = m ? cn : cold;
        float hw = m ? hn : hold;
        cbuf[b * HH + hid] = cw;
        hnext[b * HH + hid] = hw;
        if (STORE_HS) g_hs0[dir][r * HH + hid] = hw;
    }
}

// ---------------- dense head ------------------------------------------------
__global__ void k_dense0(const float* __restrict__ w, const float* __restrict__ bia) {
    int gw = (blockIdx.x * blockDim.x + threadIdx.x) >> 5;
    int lane = threadIdx.x & 31;
    if (gw >= BB * 512) return;
    int b = gw >> 9, j = gw & 511;
    float s = 0.f;
    for (int k = lane; k < KC; k += 32) {
        float a = (k < HH) ? g_h[0][0][b * HH + k] : g_h[1][0][b * HH + (k - HH)];
        s += a * w[(size_t)k * 512 + j];
    }
    #pragma unroll
    for (int o = 16; o; o >>= 1) s += __shfl_xor_sync(0xffffffffu, s, o);
    if (!lane) {
        s += bia[j];
        g_fc1[b * 512 + j] = (s >= 0.f) ? s : 0.2f * s;
    }
}

__global__ void k_dense1(const float* __restrict__ w, const float* __restrict__ bia) {
    int gw = (blockIdx.x * blockDim.x + threadIdx.x) >> 5;
    int lane = threadIdx.x & 31;
    if (gw >= BB * 256) return;
    int b = gw >> 8, j = gw & 255;
    float s = 0.f;
    for (int k = lane; k < 512; k += 32)
        s += g_fc1[b * 512 + k] * w[(size_t)k * 256 + j];
    #pragma unroll
    for (int o = 16; o; o >>= 1) s += __shfl_xor_sync(0xffffffffu, s, o);
    if (!lane) {
        s += bia[j];
        g_fc2[b * 256 + j] = (s >= 0.f) ? s : 0.2f * s;
    }
}

__global__ void k_dense2(const float* __restrict__ w, const float* __restrict__ bia,
                         float* __restrict__ out) {
    int b = blockIdx.x;
    int lane = threadIdx.x;
    float s = 0.f;
    for (int k = lane; k < 256; k += 32)
        s += g_fc2[b * 256 + k] * w[k];
    #pragma unroll
    for (int o = 16; o; o >>= 1) s += __shfl_xor_sync(0xffffffffu, s, o);
    if (!lane) out[b] = s + bia[0];
}

// ---------------- launch ----------------------------------------------------
extern "C" void kernel_launch(void* const* d_in, const int* in_sizes, int n_in,
                              void* d_out, int out_size) {
    const int*   text = (const int*)  d_in[0];
    const float* emb  = (const float*)d_in[1];
    const float* W0f  = (const float*)d_in[2];
    const float* U0f  = (const float*)d_in[3];
    const float* b0f  = (const float*)d_in[4];
    const float* W0b  = (const float*)d_in[5];
    const float* U0b  = (const float*)d_in[6];
    const float* b0b  = (const float*)d_in[7];
    const float* W1f  = (const float*)d_in[8];
    const float* U1f  = (const float*)d_in[9];
    const float* b1f  = (const float*)d_in[10];
    const float* W1b  = (const float*)d_in[11];
    const float* U1b  = (const float*)d_in[12];
    const float* b1b  = (const float*)d_in[13];
    const float* d0w  = (const float*)d_in[14];
    const float* d0b  = (const float*)d_in[15];
    const float* d1w  = (const float*)d_in[16];
    const float* d1b  = (const float*)d_in[17];
    const float* d2w  = (const float*)d_in[18];
    const float* d2b  = (const float*)d_in[19];
    float* out = (float*)d_out;

    // ---- layer 0 ----
    k_zero_state<<<128, 256>>>();
    k_gemm_xz<0><<<dim3(BB * SS / 64, GG / 64, 2), 256>>>(text, emb, W0f, b0f, W0b, b0b);
    for (int p = 0; p < SS; p++)
        k_lstm_step<true><<<dim3(HH / 8, 2), 128>>>(p, text, U0f, U0b);

    // ---- layer 1 ----
    k_zero_state<<<128, 256>>>();
    k_gemm_xz<1><<<dim3(BB * SS / 64, GG / 64, 2), 256>>>(text, emb, W1f, b1f, W1b, b1b);
    for (int p = 0; p < SS; p++)
        k_lstm_step<false><<<dim3(HH / 8, 2), 128>>>(p, text, U1f, U1b);

    // ---- dense head ----
    k_dense0<<<(BB * 512 * 32) / 256, 256>>>(d0w, d0b);
    k_dense1<<<(BB * 256 * 32) / 256, 256>>>(d1w, d1b);
    k_dense2<<<BB, 32>>>(d2w, d2b, out);
}

// round 4
// speedup vs baseline: 1.8588x; 1.8588x over previous
#include <cuda_runtime.h>
#include <cstddef>

#define BB 64
#define SS 256
#define DD 300
#define HH 512
#define GG 2048   // 4*H
#define KC 1024   // 2*H
#define NBLK 128u

typedef unsigned long long ull;

// ---------------- scratch (static device globals; no allocation) ------------
__device__ float g_xz[2][(size_t)BB * SS * GG];   // per-dir input projections
__device__ float g_hs0[2][(size_t)BB * SS * HH];  // layer-0 seq outputs (original t)
__device__ float g_hT[2][2][HH * BB];             // [dir][parity][h*BB + b] transposed h
__device__ float g_fc1[BB * 512];
__device__ float g_fc2[BB * 256];
__device__ unsigned g_bar;

__global__ void k_zero_bar() { g_bar = 0u; }

// ---------------- input-projection GEMM (unchanged, works) ------------------
template<int MODE>
__global__ void k_gemm_xz(const int* __restrict__ text,
                          const float* __restrict__ emb,
                          const float* __restrict__ Wf,
                          const float* __restrict__ bf_,
                          const float* __restrict__ Wb,
                          const float* __restrict__ bb_) {
    const int K = (MODE == 0) ? DD : KC;
    const int dir = blockIdx.z;
    const float* __restrict__ W    = dir ? Wb  : Wf;
    const float* __restrict__ bias = dir ? bb_ : bf_;
    float* __restrict__ out = g_xz[dir];

    __shared__ __align__(16) float As[16][68];
    __shared__ __align__(16) float Bs[16][68];

    const int r0 = blockIdx.x * 64;
    const int j0 = blockIdx.y * 64;
    const int tid = threadIdx.x;
    const int tx = tid & 15;
    const int ty = tid >> 4;

    float acc[4][4] = {};

    for (int k0 = 0; k0 < K; k0 += 16) {
        #pragma unroll
        for (int p = 0; p < 4; p++) {
            int kk = tid & 15;
            int rr = (tid >> 4) + p * 16;
            int k = k0 + kk;
            int r = r0 + rr;
            float v = 0.f;
            if (k < K) {
                if (MODE == 0) {
                    v = emb[(size_t)text[r] * DD + k];
                } else {
                    v = (k < HH) ? g_hs0[0][(size_t)r * HH + k]
                                 : g_hs0[1][(size_t)r * HH + (k - HH)];
                }
            }
            As[kk][rr] = v;
        }
        #pragma unroll
        for (int p = 0; p < 4; p++) {
            int jj = tid & 63;
            int kk = (tid >> 6) + p * 4;
            int k = k0 + kk;
            float v = (k < K) ? W[(size_t)k * GG + j0 + jj] : 0.f;
            Bs[kk][jj] = v;
        }
        __syncthreads();
        #pragma unroll
        for (int kk = 0; kk < 16; kk++) {
            float4 a4 = *(const float4*)&As[kk][ty * 4];
            float4 b4 = *(const float4*)&Bs[kk][tx * 4];
            float ar[4] = {a4.x, a4.y, a4.z, a4.w};
            float br[4] = {b4.x, b4.y, b4.z, b4.w};
            #pragma unroll
            for (int i = 0; i < 4; i++)
                #pragma unroll
                for (int j = 0; j < 4; j++)
                    acc[i][j] += ar[i] * br[j];
        }
        __syncthreads();
    }

    #pragma unroll
    for (int i = 0; i < 4; i++) {
        int r = r0 + ty * 4 + i;
        #pragma unroll
        for (int j = 0; j < 4; j++) {
            int c = j0 + tx * 4 + j;
            out[(size_t)r * GG + c] = acc[i][j] + bias[c];
        }
    }
}

// ---------------- persistent LSTM recurrence --------------------------------
// grid = (64, 2 dirs), block = 128, 1 block/SM (147KB smem) -> all co-resident.
// Each block owns 8 h-columns of one direction; U slice lives in SMEM duplicated
// as (u,u) f32x2 pairs for the whole sequence. c and h for owned cells live in
// registers. h is exchanged between blocks via transposed global buffers,
// double-buffered by step parity, with a software grid barrier per step.

#define FMA2(d, a, b, c) \
    asm("fma.rn.f32x2 %0, %1, %2, %3;" : "=l"(d) : "l"(a), "l"(b), "l"(c))

__device__ __forceinline__ void gridbar(unsigned epoch) {
    __syncthreads();
    if (threadIdx.x == 0) {
        __threadfence();
        atomicAdd(&g_bar, 1u);
        unsigned tgt = epoch * NBLK;
        while (atomicAdd(&g_bar, 0u) < tgt) __nanosleep(64);
    }
    __syncthreads();
}

template<bool STORE_HS>
__global__ void __launch_bounds__(128, 1) k_lstm_persist(
        const int* __restrict__ text,
        const float* __restrict__ Uf,
        const float* __restrict__ Ub) {
    extern __shared__ float sm[];
    ull*   Usd = (ull*)sm;            // [512][32] dup pairs (128KB)
    float* hsm = sm + 512 * 64;       // [64 k][64 b] tile (16KB)

    const int dir = blockIdx.y;
    const int h0  = blockIdx.x * 8;
    const float* __restrict__ U  = dir ? Ub : Uf;
    const float* __restrict__ xz = g_xz[dir];
    const int tid = threadIdx.x;
    const int tx  = tid & 7;     // h offset
    const int ty  = tid >> 3;    // batch group
    const int b0  = ty * 4;
    const int hid = h0 + tx;

    // stage duplicated U slice: Usd[k][g*8+h] = (u,u)
    for (int i = tid; i < 512 * 32; i += 128) {
        int k = i >> 5, c = i & 31, g = c >> 3, hh = c & 7;
        float u = U[(size_t)k * GG + g * HH + h0 + hh];
        ull pr;
        asm("mov.b64 %0, {%1,%2};" : "=l"(pr) : "f"(u), "f"(u));
        Usd[i] = pr;
    }

    // zero owned parity-0 h cells; c,h live in registers
    __stcg((float4*)&g_hT[dir][0][hid * BB + b0], make_float4(0.f, 0.f, 0.f, 0.f));
    float creg[4] = {0.f, 0.f, 0.f, 0.f};
    float hreg[4] = {0.f, 0.f, 0.f, 0.f};

    unsigned epoch = 0;
    gridbar(++epoch);   // zeros visible everywhere before step 0

    for (int p = 0; p < SS; p++) {
        const int t = dir ? (SS - 1 - p) : p;
        const float* __restrict__ hprev = g_hT[dir][p & 1];

        // prefetch xz + mask for this step's owned cells
        float xzr[4][4];
        int msk[4];
        #pragma unroll
        for (int ib = 0; ib < 4; ib++) {
            size_t r = (size_t)(b0 + ib) * SS + t;
            msk[ib] = text[r];
            const float* xp = xz + r * GG + hid;
            xzr[ib][0] = xp[0];
            xzr[ib][1] = xp[HH];
            xzr[ib][2] = xp[2 * HH];
            xzr[ib][3] = xp[3 * HH];
        }

        ull acc[2][4];
        #pragma unroll
        for (int q = 0; q < 2; q++)
            #pragma unroll
            for (int g = 0; g < 4; g++) acc[q][g] = 0ull;

        // prefetch h tile 0 into registers (L2-coherent loads)
        float4 pf[8];
        {
            const float4* src = (const float4*)hprev;
            #pragma unroll
            for (int i = 0; i < 8; i++) pf[i] = __ldcg(src + tid + 128 * i);
        }

        for (int k0 = 0; k0 < HH; k0 += 64) {
            __syncthreads();
            #pragma unroll
            for (int i = 0; i < 8; i++) ((float4*)hsm)[tid + 128 * i] = pf[i];
            if (k0 + 64 < HH) {
                const float4* nsrc = (const float4*)(hprev + (k0 + 64) * BB);
                #pragma unroll
                for (int i = 0; i < 8; i++) pf[i] = __ldcg(nsrc + tid + 128 * i);
            }
            __syncthreads();

            const ull* ub = Usd + (size_t)k0 * 32 + tx;
            #pragma unroll 16
            for (int kk = 0; kk < 64; kk++) {
                ulonglong2 hv = *(const ulonglong2*)&hsm[kk * 64 + b0];
                const ull* up = ub + (size_t)kk * 32;
                ull u0 = up[0], u1 = up[8], u2 = up[16], u3 = up[24];
                FMA2(acc[0][0], hv.x, u0, acc[0][0]);
                FMA2(acc[1][0], hv.y, u0, acc[1][0]);
                FMA2(acc[0][1], hv.x, u1, acc[0][1]);
                FMA2(acc[1][1], hv.y, u1, acc[1][1]);
                FMA2(acc[0][2], hv.x, u2, acc[0][2]);
                FMA2(acc[1][2], hv.y, u2, acc[1][2]);
                FMA2(acc[0][3], hv.x, u3, acc[0][3]);
                FMA2(acc[1][3], hv.y, u3, acc[1][3]);
            }
        }

        // unpack accumulators: pair0=(b0,b0+1), pair1=(b0+2,b0+3)
        float zz[4][4];
        #pragma unroll
        for (int g = 0; g < 4; g++) {
            float lo, hi;
            asm("mov.b64 {%0,%1}, %2;" : "=f"(lo), "=f"(hi) : "l"(acc[0][g]));
            zz[0][g] = lo; zz[1][g] = hi;
            asm("mov.b64 {%0,%1}, %2;" : "=f"(lo), "=f"(hi) : "l"(acc[1][g]));
            zz[2][g] = lo; zz[3][g] = hi;
        }

        #pragma unroll
        for (int ib = 0; ib < 4; ib++) {
            float zi = zz[ib][0] + xzr[ib][0];
            float zf = zz[ib][1] + xzr[ib][1];
            float zg = zz[ib][2] + xzr[ib][2];
            float zo = zz[ib][3] + xzr[ib][3];
            float ig = 1.f / (1.f + __expf(-zi));
            float fg = 1.f / (1.f + __expf(-zf));
            float gg = tanhf(zg);
            float og = 1.f / (1.f + __expf(-zo));
            float cn = fg * creg[ib] + ig * gg;
            float hn = og * tanhf(cn);
            bool m = (msk[ib] != 0);
            creg[ib] = m ? cn : creg[ib];
            hreg[ib] = m ? hn : hreg[ib];
        }

        __stcg((float4*)&g_hT[dir][(p + 1) & 1][hid * BB + b0],
               make_float4(hreg[0], hreg[1], hreg[2], hreg[3]));
        if (STORE_HS) {
            #pragma unroll
            for (int ib = 0; ib < 4; ib++)
                g_hs0[dir][((size_t)(b0 + ib) * SS + t) * HH + hid] = hreg[ib];
        }

        gridbar(++epoch);
    }
}

// ---------------- dense head ------------------------------------------------
__global__ void k_dense0(const float* __restrict__ w, const float* __restrict__ bia) {
    int gw = (blockIdx.x * blockDim.x + threadIdx.x) >> 5;
    int lane = threadIdx.x & 31;
    if (gw >= BB * 512) return;
    int b = gw >> 9, j = gw & 511;
    float s = 0.f;
    for (int k = lane; k < KC; k += 32) {
        float a = (k < HH) ? g_hT[0][0][k * BB + b]
                           : g_hT[1][0][(k - HH) * BB + b];
        s += a * w[(size_t)k * 512 + j];
    }
    #pragma unroll
    for (int o = 16; o; o >>= 1) s += __shfl_xor_sync(0xffffffffu, s, o);
    if (!lane) {
        s += bia[j];
        g_fc1[b * 512 + j] = (s >= 0.f) ? s : 0.2f * s;
    }
}

__global__ void k_dense1(const float* __restrict__ w, const float* __restrict__ bia) {
    int gw = (blockIdx.x * blockDim.x + threadIdx.x) >> 5;
    int lane = threadIdx.x & 31;
    if (gw >= BB * 256) return;
    int b = gw >> 8, j = gw & 255;
    float s = 0.f;
    for (int k = lane; k < 512; k += 32)
        s += g_fc1[b * 512 + k] * w[(size_t)k * 256 + j];
    #pragma unroll
    for (int o = 16; o; o >>= 1) s += __shfl_xor_sync(0xffffffffu, s, o);
    if (!lane) {
        s += bia[j];
        g_fc2[b * 256 + j] = (s >= 0.f) ? s : 0.2f * s;
    }
}

__global__ void k_dense2(const float* __restrict__ w, const float* __restrict__ bia,
                         float* __restrict__ out) {
    int b = blockIdx.x;
    int lane = threadIdx.x;
    float s = 0.f;
    for (int k = lane; k < 256; k += 32)
        s += g_fc2[b * 256 + k] * w[k];
    #pragma unroll
    for (int o = 16; o; o >>= 1) s += __shfl_xor_sync(0xffffffffu, s, o);
    if (!lane) out[b] = s + bia[0];
}

// ---------------- launch ----------------------------------------------------
extern "C" void kernel_launch(void* const* d_in, const int* in_sizes, int n_in,
                              void* d_out, int out_size) {
    const int*   text = (const int*)  d_in[0];
    const float* emb  = (const float*)d_in[1];
    const float* W0f  = (const float*)d_in[2];
    const float* U0f  = (const float*)d_in[3];
    const float* b0f  = (const float*)d_in[4];
    const float* W0b  = (const float*)d_in[5];
    const float* U0b  = (const float*)d_in[6];
    const float* b0b  = (const float*)d_in[7];
    const float* W1f  = (const float*)d_in[8];
    const float* U1f  = (const float*)d_in[9];
    const float* b1f  = (const float*)d_in[10];
    const float* W1b  = (const float*)d_in[11];
    const float* U1b  = (const float*)d_in[12];
    const float* b1b  = (const float*)d_in[13];
    const float* d0w  = (const float*)d_in[14];
    const float* d0b  = (const float*)d_in[15];
    const float* d1w  = (const float*)d_in[16];
    const float* d1b  = (const float*)d_in[17];
    const float* d2w  = (const float*)d_in[18];
    const float* d2b  = (const float*)d_in[19];
    float* out = (float*)d_out;

    const int smemsz = (512 * 64 + 64 * 64) * 4;  // 147456 B
    cudaFuncSetAttribute(k_lstm_persist<true>,
                         cudaFuncAttributeMaxDynamicSharedMemorySize, smemsz);
    cudaFuncSetAttribute(k_lstm_persist<false>,
                         cudaFuncAttributeMaxDynamicSharedMemorySize, smemsz);

    // ---- layer 0 ----
    k_zero_bar<<<1, 1>>>();
    k_gemm_xz<0><<<dim3(BB * SS / 64, GG / 64, 2), 256>>>(text, emb, W0f, b0f, W0b, b0b);
    k_lstm_persist<true><<<dim3(64, 2), 128, smemsz>>>(text, U0f, U0b);

    // ---- layer 1 ----
    k_zero_bar<<<1, 1>>>();
    k_gemm_xz<1><<<dim3(BB * SS / 64, GG / 64, 2), 256>>>(text, emb, W1f, b1f, W1b, b1b);
    k_lstm_persist<false><<<dim3(64, 2), 128, smemsz>>>(text, U1f, U1b);

    // ---- dense head ----
    k_dense0<<<(BB * 512 * 32) / 256, 256>>>(d0w, d0b);
    k_dense1<<<(BB * 256 * 32) / 256, 256>>>(d1w, d1b);
    k_dense2<<<BB, 32>>>(d2w, d2b, out);
}